// round 11
// baseline (speedup 1.0000x reference)
#include <cuda_runtime.h>
#include <cuda_fp16.h>
#include <cstdint>

#define BATCH 2
#define SEQ   2048
#define DM    2048
#define NH    16
#define HD    128
#define KVD   256
#define QKVN  (DM + KVD)           // 2304 merged projection width
#define MTOT  (BATCH*SEQ)

// fp16 scratch
__device__ __half g_xh[MTOT * DM];
__device__ __half g_wqkv[QKVN * DM];    // [Wq rows; Wkv rows]
__device__ __half g_woh[DM * DM];
__device__ __half g_qkv[MTOT * QKVN];   // Q cols [0,2048), K [2048,2176), V [2176,2304)
__device__ __half g_oh[MTOT * DM];

// ===========================================================================
// helpers
// ===========================================================================
__device__ __forceinline__ uint32_t smem_u32(const void* p) {
    uint32_t a;
    asm("{ .reg .u64 t; cvta.to.shared.u64 t, %1; cvt.u32.u64 %0, t; }"
        : "=r"(a) : "l"(p));
    return a;
}

#define CP16(dst, src) \
    asm volatile("cp.async.cg.shared.global [%0], [%1], 16;" \
                 :: "r"(dst), "l"(src))
#define CP_COMMIT() asm volatile("cp.async.commit_group;")
#define CP_WAIT(n)  asm volatile("cp.async.wait_group %0;" :: "n"(n))

#define LDSM4(r, addr)                                                        \
    asm volatile("ldmatrix.sync.aligned.m8n8.x4.shared.b16 {%0,%1,%2,%3}, [%4];" \
        : "=r"((r)[0]), "=r"((r)[1]), "=r"((r)[2]), "=r"((r)[3]) : "r"(addr))
#define LDSM4T(r, addr)                                                       \
    asm volatile("ldmatrix.sync.aligned.m8n8.x4.trans.shared.b16 {%0,%1,%2,%3}, [%4];" \
        : "=r"((r)[0]), "=r"((r)[1]), "=r"((r)[2]), "=r"((r)[3]) : "r"(addr))

#define MMAF16(c, a, b)                                                       \
    asm volatile("mma.sync.aligned.m16n8k16.row.col.f32.f16.f16.f32 "         \
        "{%0,%1,%2,%3}, {%4,%5,%6,%7}, {%8,%9}, {%0,%1,%2,%3};"               \
        : "+f"((c)[0]), "+f"((c)[1]), "+f"((c)[2]), "+f"((c)[3])              \
        : "r"((a)[0]), "r"((a)[1]), "r"((a)[2]), "r"((a)[3]),                 \
          "r"((b)[0]), "r"((b)[1]))

__device__ __forceinline__ uint32_t pack_h2(float a, float b) {
    __half2 h = __floats2half2_rn(a, b);
    return *(uint32_t*)&h;
}

// ===========================================================================
// merged fp32 -> fp16 conversion for all four inputs (one launch)
// ===========================================================================
#define N4_X   (MTOT * DM / 4)
#define N4_WQ  (DM * DM / 4)
#define N4_WO  (DM * DM / 4)
#define N4_WKV (KVD * DM / 4)
#define N4_ALL (N4_X + N4_WQ + N4_WO + N4_WKV)

__global__ void __launch_bounds__(256)
cvt_all(const float4* __restrict__ x,  const float4* __restrict__ wq,
        const float4* __restrict__ wo, const float4* __restrict__ wkv,
        uint2* __restrict__ xh, uint2* __restrict__ wqkv,
        uint2* __restrict__ woh)
{
    int i = blockIdx.x * blockDim.x + threadIdx.x;
    const float4* src;
    uint2* dst;
    int k = i;
    if (k < N4_X)              { src = x;   dst = xh;   }
    else if ((k -= N4_X)  < N4_WQ)  { src = wq;  dst = wqkv; }
    else if ((k -= N4_WQ) < N4_WO)  { src = wo;  dst = woh;  }
    else if ((k -= N4_WO) < N4_WKV) { src = wkv; dst = wqkv + N4_WQ; }  // uint2 units
    else return;
    float4 f = src[k];
    dst[k] = make_uint2(pack_h2(f.x, f.y), pack_h2(f.z, f.w));
}

// ===========================================================================
// fp16 mma.sync GEMM: C[M,N] = A[M,K] * B[N,K]^T
// CTA tile 256x128, 16 warps (4m x 4n), warp tile 64x32. BK=64, 3-stage
// pipeline, 1 barrier/iter. Warp-staggered ks order de-bursts the smem port.
// ===========================================================================
#define G_STRIDE 144
#define G_ABUF   (256 * G_STRIDE)          // 36864
#define G_BBUF   (128 * G_STRIDE)          // 18432
#define G_STAGE  (G_ABUF + G_BBUF)         // 55296
#define GEMM_SMEM (3 * G_STAGE)            // 165888

template<bool F16OUT>
__global__ void __launch_bounds__(512, 1)
gemm_mma(const __half* __restrict__ Ah, const __half* __restrict__ Bh,
         float* __restrict__ C, __half* __restrict__ Ch, int N, int K)
{
    extern __shared__ char smem[];
    const uint32_t sbase = smem_u32(smem);

    const int tid  = threadIdx.x;
    const int lane = tid & 31;
    const int wid  = tid >> 5;           // 0..15
    const int wm   = (wid >> 2) * 64;
    const int wn   = (wid & 3) * 32;
    const int m0   = blockIdx.y * 256;
    const int n0   = blockIdx.x * 128;

    // A load map: 256 rows x 128B; 2 threads/row, 64B (4 chunks) each
    const int arow = tid >> 1;
    const int aoff = (tid & 1) * 64;
    const __half* gA = Ah + (size_t)(m0 + arow) * K + (tid & 1) * 32;
    const uint32_t dA = arow * G_STRIDE + aoff;
    // B load map: 128 rows x 128B; 4 threads/row, 32B (2 chunks) each
    const int brow = tid >> 2;
    const int boff = (tid & 3) * 32;
    const __half* gB = Bh + (size_t)(n0 + brow) * K + (tid & 3) * 16;
    const uint32_t dB = G_ABUF + brow * G_STRIDE + boff;

    const int NIT = K >> 6;

    auto issue = [&](int kt) {
        const uint32_t s = sbase + (kt % 3) * G_STAGE;
        const int kb = kt << 6;
#pragma unroll
        for (int c = 0; c < 4; c++)
            CP16(s + dA + c * 16, gA + kb + c * 8);
#pragma unroll
        for (int c = 0; c < 2; c++)
            CP16(s + dB + c * 16, gB + kb + c * 8);
    };

    issue(0); CP_COMMIT();
    issue(1); CP_COMMIT();

    float acc[4][4][4] = {};

    for (int kt = 0; kt < NIT; kt++) {
        CP_WAIT(1);
        __syncthreads();
        if (kt + 2 < NIT) issue(kt + 2);
        CP_COMMIT();

        const uint32_t sb = sbase + (kt % 3) * G_STAGE;
#pragma unroll
        for (int ksx = 0; ksx < 4; ksx++) {
            const int ks = (ksx + wid) & 3;   // warp-staggered phase
            uint32_t a4[4][4], b2[4][2];
#pragma unroll
            for (int mi = 0; mi < 4; mi++) {
                uint32_t aaddr = sb + (wm + mi * 16 + (lane & 15)) * G_STRIDE
                               + ks * 32 + (lane >> 4) * 16;
                LDSM4(a4[mi], aaddr);
            }
#pragma unroll
            for (int np = 0; np < 2; np++) {
                uint32_t r[4];
                uint32_t baddr = sb + G_ABUF
                               + (wn + np * 16 + ((lane >> 4) << 3) + (lane & 7)) * G_STRIDE
                               + ks * 32 + ((lane >> 3) & 1) * 16;
                LDSM4(r, baddr);
                b2[np * 2][0]     = r[0]; b2[np * 2][1]     = r[1];
                b2[np * 2 + 1][0] = r[2]; b2[np * 2 + 1][1] = r[3];
            }
#pragma unroll
            for (int mi = 0; mi < 4; mi++)
#pragma unroll
                for (int ni = 0; ni < 4; ni++)
                    MMAF16(acc[mi][ni], a4[mi], b2[ni]);
        }
    }

    const int rg = lane >> 2;
    const int cg = (lane & 3) * 2;
#pragma unroll
    for (int mi = 0; mi < 4; mi++) {
#pragma unroll
        for (int ni = 0; ni < 4; ni++) {
            int r = m0 + wm + mi * 16 + rg;
            int c = n0 + wn + ni * 8 + cg;
            if (F16OUT) {
                *(uint32_t*)&Ch[(size_t)r * N + c] =
                    pack_h2(acc[mi][ni][0], acc[mi][ni][1]);
                *(uint32_t*)&Ch[(size_t)(r + 8) * N + c] =
                    pack_h2(acc[mi][ni][2], acc[mi][ni][3]);
            } else {
                *(float2*)&C[(size_t)r * N + c] =
                    make_float2(acc[mi][ni][0], acc[mi][ni][1]);
                *(float2*)&C[(size_t)(r + 8) * N + c] =
                    make_float2(acc[mi][ni][2], acc[mi][ni][3]);
            }
        }
    }
}

// ===========================================================================
// mma.sync flash attention, causal MQA, fp16. BM=128, BN=128.
// Register double-buffered K/V fragment prefetch + warp-staggered phases.
// ===========================================================================
#define AT_STRIDE 272
#define AT_BUF    (128 * AT_STRIDE)        // 34816
#define AT_STAGE  (2 * AT_BUF)             // K + V
#define AT_KV0    AT_BUF
#define ATTN_SMEM (AT_BUF + 2 * AT_STAGE)  // 174080
#define CSC 0.12751727652f                 // (1/sqrt(128)) * log2(e)

__device__ __forceinline__ void attn_kv_load(uint32_t sb, int st, int tile,
                                             int b, int tid)
{
    const int base = b * SEQ + tile * 128;
    const uint32_t kb = sb + AT_KV0 + st * AT_STAGE;
#pragma unroll
    for (int i = 0; i < 8; i++) {
        int c = tid + i * 256;
        int row = c >> 4;
        int c16 = c & 15;
        uint32_t dst = kb + row * AT_STRIDE + c16 * 16;
        size_t src = (size_t)(base + row) * QKVN + c16 * 8;
        CP16(dst,          g_qkv + src + 2048);   // K
        CP16(dst + AT_BUF, g_qkv + src + 2176);   // V
    }
}

__global__ void __launch_bounds__(256, 1)
attn_mma()
{
    extern __shared__ char smem[];
    const uint32_t sb = smem_u32(smem);

    const int tid  = threadIdx.x;
    const int lane = tid & 31;
    const int w    = tid >> 5;
    const int qb   = (int)gridDim.x - 1 - (int)blockIdx.x;
    const int b    = blockIdx.y >> 4;
    const int h    = blockIdx.y & 15;
    const int rg   = lane >> 2;
    const int qc   = lane & 3;

#pragma unroll
    for (int i = 0; i < 8; i++) {
        int c = tid + i * 256;
        int row = c >> 4;
        int c16 = c & 15;
        size_t src = (size_t)(b * SEQ + qb * 128 + row) * QKVN + h * HD + c16 * 8;
        CP16(sb + row * AT_STRIDE + c16 * 16, g_qkv + src);
    }
    CP_COMMIT();

    const int jmax = qb;
    attn_kv_load(sb, 0, 0, b, tid);
    CP_COMMIT();

    float o[16][4] = {};
    float m0 = -1e30f, m1 = -1e30f, l0 = 0.0f, l1 = 0.0f;

    for (int j = 0; j <= jmax; j++) {
        if (j < jmax) {
            attn_kv_load(sb, (j + 1) & 1, j + 1, b, tid);
            CP_COMMIT();
            CP_WAIT(1);
        } else {
            CP_WAIT(0);
        }
        __syncthreads();

        const uint32_t kvb = sb + AT_KV0 + (j & 1) * AT_STAGE;

        // ---- S = Q K^T : prefetch next K-frag during MMAs, stagger ks ----
        float s[16][4] = {};
#pragma unroll
        for (int ksx = 0; ksx < 8; ksx++) {
            const int ks = (ksx + w) & 7;
            uint32_t q4[4];
            uint32_t qaddr = sb + (w * 16 + (lane & 15)) * AT_STRIDE
                           + ks * 32 + (lane >> 4) * 16;
            LDSM4(q4, qaddr);
            const uint32_t krow = ((lane >> 4) << 3) + (lane & 7);
            const uint32_t kcol = ks * 32 + ((lane >> 3) & 1) * 16;
            uint32_t rn[4];
            LDSM4(rn, kvb + krow * AT_STRIDE + kcol);
#pragma unroll
            for (int np = 0; np < 8; np++) {
                uint32_t b0[2] = { rn[0], rn[1] };
                uint32_t b1[2] = { rn[2], rn[3] };
                if (np < 7)
                    LDSM4(rn, kvb + ((np + 1) * 16 + krow) * AT_STRIDE + kcol);
                MMAF16(s[np * 2],     q4, b0);
                MMAF16(s[np * 2 + 1], q4, b1);
            }
        }

        if (j == qb) {
            const int rbase = qb * 128 + w * 16 + rg;
            const int cbase = j * 128 + qc * 2;
#pragma unroll
            for (int nt = 0; nt < 16; nt++) {
                int c0 = cbase + nt * 8;
                if (c0 > rbase)          s[nt][0] = -1e30f;
                if (c0 + 1 > rbase)      s[nt][1] = -1e30f;
                if (c0 > rbase + 8)      s[nt][2] = -1e30f;
                if (c0 + 1 > rbase + 8)  s[nt][3] = -1e30f;
            }
        }

        float mt0 = -1e30f, mt1 = -1e30f;
#pragma unroll
        for (int nt = 0; nt < 16; nt++) {
            mt0 = fmaxf(mt0, fmaxf(s[nt][0], s[nt][1]));
            mt1 = fmaxf(mt1, fmaxf(s[nt][2], s[nt][3]));
        }
        mt0 = fmaxf(mt0, __shfl_xor_sync(0xffffffff, mt0, 1));
        mt0 = fmaxf(mt0, __shfl_xor_sync(0xffffffff, mt0, 2));
        mt1 = fmaxf(mt1, __shfl_xor_sync(0xffffffff, mt1, 1));
        mt1 = fmaxf(mt1, __shfl_xor_sync(0xffffffff, mt1, 2));

        float m0n = fmaxf(m0, mt0), m1n = fmaxf(m1, mt1);
        float a0 = exp2f((m0 - m0n) * CSC);
        float a1 = exp2f((m1 - m1n) * CSC);

        float ls0 = 0.0f, ls1 = 0.0f;
#pragma unroll
        for (int nt = 0; nt < 16; nt++) {
            s[nt][0] = exp2f((s[nt][0] - m0n) * CSC);
            s[nt][1] = exp2f((s[nt][1] - m0n) * CSC);
            s[nt][2] = exp2f((s[nt][2] - m1n) * CSC);
            s[nt][3] = exp2f((s[nt][3] - m1n) * CSC);
            ls0 += s[nt][0] + s[nt][1];
            ls1 += s[nt][2] + s[nt][3];
        }
        ls0 += __shfl_xor_sync(0xffffffff, ls0, 1);
        ls0 += __shfl_xor_sync(0xffffffff, ls0, 2);
        ls1 += __shfl_xor_sync(0xffffffff, ls1, 1);
        ls1 += __shfl_xor_sync(0xffffffff, ls1, 2);

        l0 = l0 * a0 + ls0;
        l1 = l1 * a1 + ls1;
        m0 = m0n; m1 = m1n;

#pragma unroll
        for (int nt = 0; nt < 16; nt++) {
            o[nt][0] *= a0; o[nt][1] *= a0;
            o[nt][2] *= a1; o[nt][3] *= a1;
        }

        // ---- O += P V : prefetch next V-frag during MMAs, stagger kk ----
#pragma unroll
        for (int kkx = 0; kkx < 8; kkx++) {
            const int kk = (kkx + w) & 7;
            uint32_t p4[4];
            p4[0] = pack_h2(s[2*kk][0],   s[2*kk][1]);
            p4[1] = pack_h2(s[2*kk][2],   s[2*kk][3]);
            p4[2] = pack_h2(s[2*kk+1][0], s[2*kk+1][1]);
            p4[3] = pack_h2(s[2*kk+1][2], s[2*kk+1][3]);
            const uint32_t vrow = kk * 16 + (lane & 15);
            const uint32_t vcol = (lane >> 4) * 16;
            uint32_t rn[4];
            LDSM4T(rn, kvb + AT_BUF + vrow * AT_STRIDE + vcol);
#pragma unroll
            for (int np = 0; np < 8; np++) {
                uint32_t v0[2] = { rn[0], rn[1] };
                uint32_t v1[2] = { rn[2], rn[3] };
                if (np < 7)
                    LDSM4T(rn, kvb + AT_BUF + vrow * AT_STRIDE
                               + (np + 1) * 32 + vcol);
                MMAF16(o[np * 2],     p4, v0);
                MMAF16(o[np * 2 + 1], p4, v1);
            }
        }
        __syncthreads();
    }

    const float inv0 = 1.0f / l0;
    const float inv1 = 1.0f / l1;
    const size_t row0 = (size_t)(b * SEQ + qb * 128 + w * 16 + rg) * DM;
    const size_t row1 = row0 + 8 * DM;
#pragma unroll
    for (int nt = 0; nt < 16; nt++) {
        int col = h * HD + nt * 8 + qc * 2;
        *(uint32_t*)&g_oh[row0 + col] = pack_h2(o[nt][0] * inv0, o[nt][1] * inv0);
        *(uint32_t*)&g_oh[row1 + col] = pack_h2(o[nt][2] * inv1, o[nt][3] * inv1);
    }
}

// ===========================================================================
extern "C" void kernel_launch(void* const* d_in, const int* in_sizes, int n_in,
                              void* d_out, int out_size)
{
    const float* x   = (const float*)d_in[0];
    const float* Wq  = (const float*)d_in[1];
    const float* Wkv = (const float*)d_in[2];
    const float* Wo  = (const float*)d_in[3];
    float* out = (float*)d_out;

    __half *xh, *wqkv, *woh, *qkv, *oh;
    cudaGetSymbolAddress((void**)&xh,   g_xh);
    cudaGetSymbolAddress((void**)&wqkv, g_wqkv);
    cudaGetSymbolAddress((void**)&woh,  g_woh);
    cudaGetSymbolAddress((void**)&qkv,  g_qkv);
    cudaGetSymbolAddress((void**)&oh,   g_oh);

    cudaFuncSetAttribute(gemm_mma<false>,
                         cudaFuncAttributeMaxDynamicSharedMemorySize, GEMM_SMEM);
    cudaFuncSetAttribute(gemm_mma<true>,
                         cudaFuncAttributeMaxDynamicSharedMemorySize, GEMM_SMEM);
    cudaFuncSetAttribute(attn_mma,
                         cudaFuncAttributeMaxDynamicSharedMemorySize, ATTN_SMEM);

    // convert all fp32 inputs to fp16 in one launch
    cvt_all<<<(N4_ALL + 255) / 256, 256>>>(
        (const float4*)x, (const float4*)Wq, (const float4*)Wo,
        (const float4*)Wkv, (uint2*)xh, (uint2*)wqkv, (uint2*)woh);

    // merged Q+KV projection -> fp16 [MTOT, 2304]
    gemm_mma<true><<<dim3(QKVN / 128, MTOT / 256), 512, GEMM_SMEM>>>(
        xh, wqkv, nullptr, qkv, QKVN, DM);
    // attention -> fp16 [MTOT, 2048]
    attn_mma<<<dim3(SEQ / 128, BATCH * NH), 256, ATTN_SMEM>>>();
    // O projection -> fp32 output
    gemm_mma<false><<<dim3(DM / 128, MTOT / 256), 512, GEMM_SMEM>>>(
        oh, woh, out, nullptr, DM, DM);
}

// round 12
// speedup vs baseline: 1.2534x; 1.2534x over previous
#include <cuda_runtime.h>
#include <cuda_fp16.h>
#include <cstdint>

#define BATCH 2
#define SEQ   2048
#define DM    2048
#define NH    16
#define HD    128
#define KVD   256
#define QKVN  (DM + KVD)           // 2304 merged projection width
#define MTOT  (BATCH*SEQ)

// fp16 scratch
__device__ __half g_xh[MTOT * DM];
__device__ __half g_wqkv[QKVN * DM];    // [Wq rows; Wkv rows]
__device__ __half g_woh[DM * DM];
__device__ __half g_qkv[MTOT * QKVN];   // Q cols [0,2048), K [2048,2176), V [2176,2304)
__device__ __half g_oh[MTOT * DM];

// ===========================================================================
// helpers
// ===========================================================================
__device__ __forceinline__ uint32_t smem_u32(const void* p) {
    uint32_t a;
    asm("{ .reg .u64 t; cvta.to.shared.u64 t, %1; cvt.u32.u64 %0, t; }"
        : "=r"(a) : "l"(p));
    return a;
}

#define CP16(dst, src) \
    asm volatile("cp.async.cg.shared.global [%0], [%1], 16;" \
                 :: "r"(dst), "l"(src))
#define CP_COMMIT() asm volatile("cp.async.commit_group;")
#define CP_WAIT(n)  asm volatile("cp.async.wait_group %0;" :: "n"(n))

#define LDSM4(r, addr)                                                        \
    asm volatile("ldmatrix.sync.aligned.m8n8.x4.shared.b16 {%0,%1,%2,%3}, [%4];" \
        : "=r"((r)[0]), "=r"((r)[1]), "=r"((r)[2]), "=r"((r)[3]) : "r"(addr))
#define LDSM4T(r, addr)                                                       \
    asm volatile("ldmatrix.sync.aligned.m8n8.x4.trans.shared.b16 {%0,%1,%2,%3}, [%4];" \
        : "=r"((r)[0]), "=r"((r)[1]), "=r"((r)[2]), "=r"((r)[3]) : "r"(addr))

#define MMAF16(c, a, b)                                                       \
    asm volatile("mma.sync.aligned.m16n8k16.row.col.f32.f16.f16.f32 "         \
        "{%0,%1,%2,%3}, {%4,%5,%6,%7}, {%8,%9}, {%0,%1,%2,%3};"               \
        : "+f"((c)[0]), "+f"((c)[1]), "+f"((c)[2]), "+f"((c)[3])              \
        : "r"((a)[0]), "r"((a)[1]), "r"((a)[2]), "r"((a)[3]),                 \
          "r"((b)[0]), "r"((b)[1]))

__device__ __forceinline__ uint32_t pack_h2(float a, float b) {
    __half2 h = __floats2half2_rn(a, b);
    return *(uint32_t*)&h;
}

// ===========================================================================
// merged fp32 -> fp16 conversion for all four inputs (one launch)
// ===========================================================================
#define N4_X   (MTOT * DM / 4)
#define N4_WQ  (DM * DM / 4)
#define N4_WO  (DM * DM / 4)
#define N4_WKV (KVD * DM / 4)
#define N4_ALL (N4_X + N4_WQ + N4_WO + N4_WKV)

__global__ void __launch_bounds__(256)
cvt_all(const float4* __restrict__ x,  const float4* __restrict__ wq,
        const float4* __restrict__ wo, const float4* __restrict__ wkv,
        uint2* __restrict__ xh, uint2* __restrict__ wqkv,
        uint2* __restrict__ woh)
{
    int i = blockIdx.x * blockDim.x + threadIdx.x;
    const float4* src;
    uint2* dst;
    int k = i;
    if (k < N4_X)              { src = x;   dst = xh;   }
    else if ((k -= N4_X)  < N4_WQ)  { src = wq;  dst = wqkv; }
    else if ((k -= N4_WQ) < N4_WO)  { src = wo;  dst = woh;  }
    else if ((k -= N4_WO) < N4_WKV) { src = wkv; dst = wqkv + N4_WQ; }  // uint2 units
    else return;
    float4 f = src[k];
    dst[k] = make_uint2(pack_h2(f.x, f.y), pack_h2(f.z, f.w));
}

// ===========================================================================
// fp16 mma.sync GEMM: C[M,N] = A[M,K] * B[N,K]^T
// CTA tile 256x128, 16 warps (4m x 4n), warp tile 64x32. BK=64, 3-stage
// pipeline, 1 barrier/iter. Row stride 144B. (exact R10 version)
// ===========================================================================
#define G_STRIDE 144
#define G_ABUF   (256 * G_STRIDE)          // 36864
#define G_BBUF   (128 * G_STRIDE)          // 18432
#define G_STAGE  (G_ABUF + G_BBUF)         // 55296
#define GEMM_SMEM (3 * G_STAGE)            // 165888

template<bool F16OUT>
__global__ void __launch_bounds__(512, 1)
gemm_mma(const __half* __restrict__ Ah, const __half* __restrict__ Bh,
         float* __restrict__ C, __half* __restrict__ Ch, int N, int K)
{
    extern __shared__ char smem[];
    const uint32_t sbase = smem_u32(smem);

    const int tid  = threadIdx.x;
    const int lane = tid & 31;
    const int wid  = tid >> 5;           // 0..15
    const int wm   = (wid >> 2) * 64;
    const int wn   = (wid & 3) * 32;
    const int m0   = blockIdx.y * 256;
    const int n0   = blockIdx.x * 128;

    const int arow = tid >> 1;
    const int aoff = (tid & 1) * 64;
    const __half* gA = Ah + (size_t)(m0 + arow) * K + (tid & 1) * 32;
    const uint32_t dA = arow * G_STRIDE + aoff;
    const int brow = tid >> 2;
    const int boff = (tid & 3) * 32;
    const __half* gB = Bh + (size_t)(n0 + brow) * K + (tid & 3) * 16;
    const uint32_t dB = G_ABUF + brow * G_STRIDE + boff;

    const int NIT = K >> 6;

    auto issue = [&](int kt) {
        const uint32_t s = sbase + (kt % 3) * G_STAGE;
        const int kb = kt << 6;
#pragma unroll
        for (int c = 0; c < 4; c++)
            CP16(s + dA + c * 16, gA + kb + c * 8);
#pragma unroll
        for (int c = 0; c < 2; c++)
            CP16(s + dB + c * 16, gB + kb + c * 8);
    };

    issue(0); CP_COMMIT();
    issue(1); CP_COMMIT();

    float acc[4][4][4] = {};

    for (int kt = 0; kt < NIT; kt++) {
        CP_WAIT(1);
        __syncthreads();
        if (kt + 2 < NIT) issue(kt + 2);
        CP_COMMIT();

        const uint32_t sb = sbase + (kt % 3) * G_STAGE;
#pragma unroll
        for (int ks = 0; ks < 4; ks++) {
            uint32_t a4[4][4], b2[4][2];
#pragma unroll
            for (int mi = 0; mi < 4; mi++) {
                uint32_t aaddr = sb + (wm + mi * 16 + (lane & 15)) * G_STRIDE
                               + ks * 32 + (lane >> 4) * 16;
                LDSM4(a4[mi], aaddr);
            }
#pragma unroll
            for (int np = 0; np < 2; np++) {
                uint32_t r[4];
                uint32_t baddr = sb + G_ABUF
                               + (wn + np * 16 + ((lane >> 4) << 3) + (lane & 7)) * G_STRIDE
                               + ks * 32 + ((lane >> 3) & 1) * 16;
                LDSM4(r, baddr);
                b2[np * 2][0]     = r[0]; b2[np * 2][1]     = r[1];
                b2[np * 2 + 1][0] = r[2]; b2[np * 2 + 1][1] = r[3];
            }
#pragma unroll
            for (int mi = 0; mi < 4; mi++)
#pragma unroll
                for (int ni = 0; ni < 4; ni++)
                    MMAF16(acc[mi][ni], a4[mi], b2[ni]);
        }
    }

    const int rg = lane >> 2;
    const int cg = (lane & 3) * 2;
#pragma unroll
    for (int mi = 0; mi < 4; mi++) {
#pragma unroll
        for (int ni = 0; ni < 4; ni++) {
            int r = m0 + wm + mi * 16 + rg;
            int c = n0 + wn + ni * 8 + cg;
            if (F16OUT) {
                *(uint32_t*)&Ch[(size_t)r * N + c] =
                    pack_h2(acc[mi][ni][0], acc[mi][ni][1]);
                *(uint32_t*)&Ch[(size_t)(r + 8) * N + c] =
                    pack_h2(acc[mi][ni][2], acc[mi][ni][3]);
            } else {
                *(float2*)&C[(size_t)r * N + c] =
                    make_float2(acc[mi][ni][0], acc[mi][ni][1]);
                *(float2*)&C[(size_t)(r + 8) * N + c] =
                    make_float2(acc[mi][ni][2], acc[mi][ni][3]);
            }
        }
    }
}

// ===========================================================================
// mma.sync flash attention, causal MQA, fp16. BM=128, BN=128.
// R10 structure + ONE change: Q fragments hoisted to registers (loaded once).
// ===========================================================================
#define AT_STRIDE 272
#define AT_BUF    (128 * AT_STRIDE)        // 34816
#define AT_STAGE  (2 * AT_BUF)             // K + V
#define AT_KV0    AT_BUF
#define ATTN_SMEM (AT_BUF + 2 * AT_STAGE)  // 174080
#define CSC 0.12751727652f                 // (1/sqrt(128)) * log2(e)

__device__ __forceinline__ void attn_kv_load(uint32_t sb, int st, int tile,
                                             int b, int tid)
{
    const int base = b * SEQ + tile * 128;
    const uint32_t kb = sb + AT_KV0 + st * AT_STAGE;
#pragma unroll
    for (int i = 0; i < 8; i++) {
        int c = tid + i * 256;
        int row = c >> 4;
        int c16 = c & 15;
        uint32_t dst = kb + row * AT_STRIDE + c16 * 16;
        size_t src = (size_t)(base + row) * QKVN + c16 * 8;
        CP16(dst,          g_qkv + src + 2048);   // K
        CP16(dst + AT_BUF, g_qkv + src + 2176);   // V
    }
}

__global__ void __launch_bounds__(256, 1)
attn_mma()
{
    extern __shared__ char smem[];
    const uint32_t sb = smem_u32(smem);

    const int tid  = threadIdx.x;
    const int lane = tid & 31;
    const int w    = tid >> 5;
    const int qb   = (int)gridDim.x - 1 - (int)blockIdx.x;
    const int b    = blockIdx.y >> 4;
    const int h    = blockIdx.y & 15;
    const int rg   = lane >> 2;
    const int qc   = lane & 3;

    // stage Q into smem (transient — only read once into registers)
#pragma unroll
    for (int i = 0; i < 8; i++) {
        int c = tid + i * 256;
        int row = c >> 4;
        int c16 = c & 15;
        size_t src = (size_t)(b * SEQ + qb * 128 + row) * QKVN + h * HD + c16 * 8;
        CP16(sb + row * AT_STRIDE + c16 * 16, g_qkv + src);
    }
    CP_COMMIT();

    const int jmax = qb;
    attn_kv_load(sb, 0, 0, b, tid);
    CP_COMMIT();

    // wait for Q (KV0 may still be in flight), then hoist Q frags to regs
    CP_WAIT(1);
    __syncthreads();
    uint32_t qreg[8][4];
#pragma unroll
    for (int ks = 0; ks < 8; ks++) {
        uint32_t qaddr = sb + (w * 16 + (lane & 15)) * AT_STRIDE
                       + ks * 32 + (lane >> 4) * 16;
        LDSM4(qreg[ks], qaddr);
    }

    float o[16][4] = {};
    float m0 = -1e30f, m1 = -1e30f, l0 = 0.0f, l1 = 0.0f;

    for (int j = 0; j <= jmax; j++) {
        if (j < jmax) {
            attn_kv_load(sb, (j + 1) & 1, j + 1, b, tid);
            CP_COMMIT();
            CP_WAIT(1);
        } else {
            CP_WAIT(0);
        }
        __syncthreads();

        const uint32_t kvb = sb + AT_KV0 + (j & 1) * AT_STAGE;

        // ---- S = Q K^T : Q from registers, K from smem ----
        float s[16][4] = {};
#pragma unroll
        for (int ks = 0; ks < 8; ks++) {
#pragma unroll
            for (int np = 0; np < 8; np++) {
                uint32_t r[4];
                uint32_t kaddr = kvb
                               + (np * 16 + ((lane >> 4) << 3) + (lane & 7)) * AT_STRIDE
                               + ks * 32 + ((lane >> 3) & 1) * 16;
                LDSM4(r, kaddr);
                uint32_t b0[2] = { r[0], r[1] };
                uint32_t b1[2] = { r[2], r[3] };
                MMAF16(s[np * 2],     qreg[ks], b0);
                MMAF16(s[np * 2 + 1], qreg[ks], b1);
            }
        }

        if (j == qb) {
            const int rbase = qb * 128 + w * 16 + rg;
            const int cbase = j * 128 + qc * 2;
#pragma unroll
            for (int nt = 0; nt < 16; nt++) {
                int c0 = cbase + nt * 8;
                if (c0 > rbase)          s[nt][0] = -1e30f;
                if (c0 + 1 > rbase)      s[nt][1] = -1e30f;
                if (c0 > rbase + 8)      s[nt][2] = -1e30f;
                if (c0 + 1 > rbase + 8)  s[nt][3] = -1e30f;
            }
        }

        float mt0 = -1e30f, mt1 = -1e30f;
#pragma unroll
        for (int nt = 0; nt < 16; nt++) {
            mt0 = fmaxf(mt0, fmaxf(s[nt][0], s[nt][1]));
            mt1 = fmaxf(mt1, fmaxf(s[nt][2], s[nt][3]));
        }
        mt0 = fmaxf(mt0, __shfl_xor_sync(0xffffffff, mt0, 1));
        mt0 = fmaxf(mt0, __shfl_xor_sync(0xffffffff, mt0, 2));
        mt1 = fmaxf(mt1, __shfl_xor_sync(0xffffffff, mt1, 1));
        mt1 = fmaxf(mt1, __shfl_xor_sync(0xffffffff, mt1, 2));

        float m0n = fmaxf(m0, mt0), m1n = fmaxf(m1, mt1);
        float a0 = exp2f((m0 - m0n) * CSC);
        float a1 = exp2f((m1 - m1n) * CSC);

        float ls0 = 0.0f, ls1 = 0.0f;
#pragma unroll
        for (int nt = 0; nt < 16; nt++) {
            s[nt][0] = exp2f((s[nt][0] - m0n) * CSC);
            s[nt][1] = exp2f((s[nt][1] - m0n) * CSC);
            s[nt][2] = exp2f((s[nt][2] - m1n) * CSC);
            s[nt][3] = exp2f((s[nt][3] - m1n) * CSC);
            ls0 += s[nt][0] + s[nt][1];
            ls1 += s[nt][2] + s[nt][3];
        }
        ls0 += __shfl_xor_sync(0xffffffff, ls0, 1);
        ls0 += __shfl_xor_sync(0xffffffff, ls0, 2);
        ls1 += __shfl_xor_sync(0xffffffff, ls1, 1);
        ls1 += __shfl_xor_sync(0xffffffff, ls1, 2);

        l0 = l0 * a0 + ls0;
        l1 = l1 * a1 + ls1;
        m0 = m0n; m1 = m1n;

#pragma unroll
        for (int nt = 0; nt < 16; nt++) {
            o[nt][0] *= a0; o[nt][1] *= a0;
            o[nt][2] *= a1; o[nt][3] *= a1;
        }

        // ---- O += P V ---- (R10 version)
#pragma unroll
        for (int kk = 0; kk < 8; kk++) {
            uint32_t p4[4];
            p4[0] = pack_h2(s[2*kk][0],   s[2*kk][1]);
            p4[1] = pack_h2(s[2*kk][2],   s[2*kk][3]);
            p4[2] = pack_h2(s[2*kk+1][0], s[2*kk+1][1]);
            p4[3] = pack_h2(s[2*kk+1][2], s[2*kk+1][3]);
#pragma unroll
            for (int np = 0; np < 8; np++) {
                uint32_t r[4];
                uint32_t vaddr = kvb + AT_BUF
                               + (kk * 16 + (lane & 15)) * AT_STRIDE
                               + (np * 2 + (lane >> 4)) * 16;
                LDSM4T(r, vaddr);
                uint32_t v0[2] = { r[0], r[1] };
                uint32_t v1[2] = { r[2], r[3] };
                MMAF16(o[np * 2],     p4, v0);
                MMAF16(o[np * 2 + 1], p4, v1);
            }
        }
        __syncthreads();
    }

    const float inv0 = 1.0f / l0;
    const float inv1 = 1.0f / l1;
    const size_t row0 = (size_t)(b * SEQ + qb * 128 + w * 16 + rg) * DM;
    const size_t row1 = row0 + 8 * DM;
#pragma unroll
    for (int nt = 0; nt < 16; nt++) {
        int col = h * HD + nt * 8 + qc * 2;
        *(uint32_t*)&g_oh[row0 + col] = pack_h2(o[nt][0] * inv0, o[nt][1] * inv0);
        *(uint32_t*)&g_oh[row1 + col] = pack_h2(o[nt][2] * inv1, o[nt][3] * inv1);
    }
}

// ===========================================================================
extern "C" void kernel_launch(void* const* d_in, const int* in_sizes, int n_in,
                              void* d_out, int out_size)
{
    const float* x   = (const float*)d_in[0];
    const float* Wq  = (const float*)d_in[1];
    const float* Wkv = (const float*)d_in[2];
    const float* Wo  = (const float*)d_in[3];
    float* out = (float*)d_out;

    __half *xh, *wqkv, *woh, *qkv, *oh;
    cudaGetSymbolAddress((void**)&xh,   g_xh);
    cudaGetSymbolAddress((void**)&wqkv, g_wqkv);
    cudaGetSymbolAddress((void**)&woh,  g_woh);
    cudaGetSymbolAddress((void**)&qkv,  g_qkv);
    cudaGetSymbolAddress((void**)&oh,   g_oh);

    cudaFuncSetAttribute(gemm_mma<false>,
                         cudaFuncAttributeMaxDynamicSharedMemorySize, GEMM_SMEM);
    cudaFuncSetAttribute(gemm_mma<true>,
                         cudaFuncAttributeMaxDynamicSharedMemorySize, GEMM_SMEM);
    cudaFuncSetAttribute(attn_mma,
                         cudaFuncAttributeMaxDynamicSharedMemorySize, ATTN_SMEM);

    // convert all fp32 inputs to fp16 in one launch
    cvt_all<<<(N4_ALL + 255) / 256, 256>>>(
        (const float4*)x, (const float4*)Wq, (const float4*)Wo,
        (const float4*)Wkv, (uint2*)xh, (uint2*)wqkv, (uint2*)woh);

    // merged Q+KV projection -> fp16 [MTOT, 2304]
    gemm_mma<true><<<dim3(QKVN / 128, MTOT / 256), 512, GEMM_SMEM>>>(
        xh, wqkv, nullptr, qkv, QKVN, DM);
    // attention -> fp16 [MTOT, 2048]
    attn_mma<<<dim3(SEQ / 128, BATCH * NH), 256, ATTN_SMEM>>>();
    // O projection -> fp32 output
    gemm_mma<false><<<dim3(DM / 128, MTOT / 256), 512, GEMM_SMEM>>>(
        oh, woh, out, nullptr, DM, DM);
}